// round 1
// baseline (speedup 1.0000x reference)
#include <cuda_runtime.h>

// Problem constants
#define NN    512
#define TT    64
#define DIN   1024
#define DOUT  1024
#define MTOT  (NN * TT)          // 32768

// Scratch (device globals: the sanctioned no-alloc scratch mechanism)
__device__ float g_wn[DOUT * DIN];          // BN-folded weight, 4 MB
__device__ float g_bstep[DOUT];             // b_norm / T
__device__ float g_pot[(size_t)MTOT * DOUT];// pot_in, 128 MB

// ---------------------------------------------------------------------------
// Prep: fold BN into weights.  ratio = gamma / sqrt(var)  (no eps, per source)
// b_step = ((bias - mean) * ratio + beta) / T
// ---------------------------------------------------------------------------
__global__ void prep_kernel(const float* __restrict__ w,
                            const float* __restrict__ bias,
                            const float* __restrict__ gamma,
                            const float* __restrict__ beta,
                            const float* __restrict__ mean,
                            const float* __restrict__ var) {
    const int o = blockIdx.x;            // 1024 blocks
    const float ratio = gamma[o] / sqrtf(var[o]);
    if (threadIdx.x == 0) {
        g_bstep[o] = ((bias[o] - mean[o]) * ratio + beta[o]) * (1.0f / (float)TT);
    }
    const float* wr = w + (size_t)o * DIN;
    float* wo = g_wn + (size_t)o * DIN;
    for (int k = threadIdx.x; k < DIN; k += blockDim.x) {
        wo[k] = wr[k] * ratio;
    }
}

// ---------------------------------------------------------------------------
// SGEMM: C[m, o] = sum_k A[m,k] * Wn[o,k]
// A = input_feature_st flattened (MTOT x DIN), Wn = g_wn (DOUT x DIN), C = g_pot
// Tiles: 128x128x16, 256 threads, 8x8 per thread.
// Warp layout: 8 warps as 4(rows) x 2(cols); warp tile 32x64.
// Lane layout: (lane>>3) -> 4 row-quads at +0/+16, (lane&7) -> 8 col-quads at +0/+32
//   => LDS.128 fetches are conflict-free (16B-strided address groups).
// ---------------------------------------------------------------------------
__global__ __launch_bounds__(256, 2)
void sgemm_kernel(const float* __restrict__ A) {
    __shared__ float As[16][132];   // [k][m], padded
    __shared__ float Bs[16][132];   // [k][n], padded

    const int tid  = threadIdx.x;
    const int m0   = blockIdx.x * 128;
    const int n0   = blockIdx.y * 128;
    const int warp = tid >> 5;
    const int lane = tid & 31;
    const int wr   = warp >> 1;     // 0..3
    const int wc   = warp & 1;      // 0..1
    const int rbase = wr * 32 + ((lane >> 3) << 2);  // row quad base
    const int cbase = wc * 64 + ((lane & 7) << 2);   // col quad base

    const float* gA = A    + (size_t)m0 * DIN;
    const float* gB = g_wn + (size_t)n0 * DIN;

    const int lrow0 = tid >> 2;          // 0..63
    const int lcg   = (tid & 3) << 2;    // 0,4,8,12

    float acc[8][8];
#pragma unroll
    for (int i = 0; i < 8; i++)
#pragma unroll
        for (int j = 0; j < 8; j++) acc[i][j] = 0.0f;

    for (int k0 = 0; k0 < DIN; k0 += 16) {
#pragma unroll
        for (int s = 0; s < 2; s++) {
            const int row = lrow0 + s * 64;
            const float4 va = *(const float4*)(gA + (size_t)row * DIN + k0 + lcg);
            As[lcg + 0][row] = va.x;
            As[lcg + 1][row] = va.y;
            As[lcg + 2][row] = va.z;
            As[lcg + 3][row] = va.w;
            const float4 vb = *(const float4*)(gB + (size_t)row * DIN + k0 + lcg);
            Bs[lcg + 0][row] = vb.x;
            Bs[lcg + 1][row] = vb.y;
            Bs[lcg + 2][row] = vb.z;
            Bs[lcg + 3][row] = vb.w;
        }
        __syncthreads();

#pragma unroll
        for (int k = 0; k < 16; k++) {
            float a[8], b[8];
            *(float4*)&a[0] = *(const float4*)&As[k][rbase];
            *(float4*)&a[4] = *(const float4*)&As[k][rbase + 16];
            *(float4*)&b[0] = *(const float4*)&Bs[k][cbase];
            *(float4*)&b[4] = *(const float4*)&Bs[k][cbase + 32];
#pragma unroll
            for (int i = 0; i < 8; i++)
#pragma unroll
                for (int j = 0; j < 8; j++)
                    acc[i][j] = fmaf(a[i], b[j], acc[i][j]);
        }
        __syncthreads();
    }

    float* C = g_pot + (size_t)m0 * DOUT + n0;
#pragma unroll
    for (int i = 0; i < 8; i++) {
        const int r = rbase + (i & 3) + ((i >> 2) << 4);  // +0..3 and +16..19
        float4 v0, v1;
        v0.x = acc[i][0]; v0.y = acc[i][1]; v0.z = acc[i][2]; v0.w = acc[i][3];
        v1.x = acc[i][4]; v1.y = acc[i][5]; v1.z = acc[i][6]; v1.w = acc[i][7];
        *(float4*)(C + (size_t)r * DOUT + cbase)      = v0;
        *(float4*)(C + (size_t)r * DOUT + cbase + 32) = v1;
    }
}

// ---------------------------------------------------------------------------
// Integrate-and-fire scan over T. One thread per (n, o).
// pot = (pot + p_t) + bstep   (left-assoc, matches reference)
// spk = pot >= 1 ; pot -= spk ; count += spk
// ---------------------------------------------------------------------------
__global__ __launch_bounds__(256)
void scan_kernel(float* __restrict__ spike_out, float* __restrict__ count_out) {
    const int idx = blockIdx.x * blockDim.x + threadIdx.x;  // 0 .. NN*DOUT-1
    const int o = idx & (DOUT - 1);
    const int n = idx >> 10;

    const float bs = g_bstep[o];
    const float* p  = g_pot      + (size_t)n * TT * DOUT + o;
    float* so       = spike_out  + (size_t)n * TT * DOUT + o;

    float pot = 0.0f;
    float cnt = 0.0f;
#pragma unroll 8
    for (int t = 0; t < TT; t++) {
        pot = (pot + p[(size_t)t * DOUT]) + bs;
        const float s = (pot >= 1.0f) ? 1.0f : 0.0f;
        so[(size_t)t * DOUT] = s;
        pot -= s;
        cnt += s;
    }
    count_out[idx] = cnt;
}

// ---------------------------------------------------------------------------
// Launch
// ---------------------------------------------------------------------------
extern "C" void kernel_launch(void* const* d_in, const int* in_sizes, int n_in,
                              void* d_out, int out_size) {
    (void)in_sizes; (void)n_in; (void)out_size;

    const float* x_st  = (const float*)d_in[0];  // (512, 64, 1024) binary
    // d_in[1] = input_features_sc : ANN path not returned -> unused
    const float* w     = (const float*)d_in[2];
    const float* bias  = (const float*)d_in[3];
    const float* gamma = (const float*)d_in[4];
    const float* beta  = (const float*)d_in[5];
    const float* mean  = (const float*)d_in[6];
    const float* var   = (const float*)d_in[7];

    float* out       = (float*)d_out;
    float* spike_out = out;                                 // 512*64*1024
    float* count_out = out + (size_t)MTOT * DOUT;           // 512*1024

    prep_kernel<<<DOUT, 256>>>(w, bias, gamma, beta, mean, var);

    dim3 grid(MTOT / 128, DOUT / 128);                      // 256 x 8
    sgemm_kernel<<<grid, 256>>>(x_st);

    scan_kernel<<<(NN * DOUT) / 256, 256>>>(spike_out, count_out);
}